// round 4
// baseline (speedup 1.0000x reference)
#include <cuda_runtime.h>
#include <cuda_bf16.h>
#include <mma.h>
#include <cstdint>

using namespace nvcuda;

#define B_ROWS 32768
#define FDIM   512
#define NCOLS  1024
#define NCLS   1000

#define BM 128
#define BN 128
#define BK 32
#define LDA 40              // bf16 smem pitch (80B)
#define NIT 48              // 3 passes * (512/32)
#define STAGE_BYTES 20480   // A(128*80) + W(128*80)
#define NSTAGE 3
#define SMEM_GEMM (NSTAGE * STAGE_BYTES)   // 61440

// scatter smem byte offsets
#define SC_WSM   0              // [32][1024] f
#define SC_OFF   131072         // int[1001]
#define SC_SRC   135168         // int[1024]
#define SC_GP    139264         // [32][16] f
#define SC_BIAS  141312         // [1024] f
#define SMEM_SCAT 145408

// ---- device globals (legal scratch) ----
__device__ int   g_cls_off[NCLS + 1];
__device__ int   g_cls_src[NCOLS];
__device__ __nv_bfloat16 g_Ahi[(size_t)B_ROWS * FDIM];
__device__ __nv_bfloat16 g_Alo[(size_t)B_ROWS * FDIM];
__device__ __nv_bfloat16 g_Whi[NCOLS * FDIM];
__device__ __nv_bfloat16 g_Wlo[NCOLS * FDIM];
__device__ float g_scratch[(size_t)B_ROWS * NCOLS];

__device__ __forceinline__ uint32_t smem_u32(const void* p) {
    uint32_t a;
    asm("{ .reg .u64 t; cvta.to.shared.u64 t, %1; cvt.u32.u64 %0, t; }" : "=r"(a) : "l"(p));
    return a;
}
__device__ __forceinline__ void cp16(uint32_t dst, const void* src) {
    asm volatile("cp.async.cg.shared.global [%0], [%1], 16;" :: "r"(dst), "l"(src) : "memory");
}

// ---- prep: deterministic CSR of label_ids ----
__global__ void prep_kernel(const int* __restrict__ label_ids) {
    __shared__ int lab[NCOLS];
    __shared__ int cnt[NCLS];
    __shared__ int off[NCLS + 1];
    int t = threadIdx.x;
    lab[t] = label_ids[t];
    __syncthreads();
    if (t < NCLS) {
        int c = 0;
        for (int i = 0; i < NCOLS; i++) c += (lab[i] == t);
        cnt[t] = c;
    }
    __syncthreads();
    if (t == 0) {
        int acc = 0;
        for (int c = 0; c < NCLS; c++) { off[c] = acc; acc += cnt[c]; }
        off[NCLS] = acc;
    }
    __syncthreads();
    if (t <= NCLS) g_cls_off[t] = off[t];
    if (t < NCLS) {
        int pos = off[t];
        for (int i = 0; i < NCOLS; i++)
            if (lab[i] == t) g_cls_src[pos++] = i;
    }
}

// ---- prep: fp32 -> bf16 hi/lo (4 elems/thread) ----
__global__ void prep_split(const float* __restrict__ src,
                           __nv_bfloat16* __restrict__ hi,
                           __nv_bfloat16* __restrict__ lo) {
    size_t i0 = ((size_t)blockIdx.x * 256 + threadIdx.x) * 4;
    float4 v = *(const float4*)(src + i0);
    __nv_bfloat16 h[4], l[4];
    float x;
    x = v.x; h[0] = __float2bfloat16_rn(x); l[0] = __float2bfloat16_rn(x - __bfloat162float(h[0]));
    x = v.y; h[1] = __float2bfloat16_rn(x); l[1] = __float2bfloat16_rn(x - __bfloat162float(h[1]));
    x = v.z; h[2] = __float2bfloat16_rn(x); l[2] = __float2bfloat16_rn(x - __bfloat162float(h[2]));
    x = v.w; h[3] = __float2bfloat16_rn(x); l[3] = __float2bfloat16_rn(x - __bfloat162float(h[3]));
    *(uint2*)(hi + i0) = *(uint2*)h;
    *(uint2*)(lo + i0) = *(uint2*)l;
}

// ---- GEMM: bf16 WMMA, 3-product split, 3-stage cp.async ring, raw logits -> scratch ----
__global__ void __launch_bounds__(256, 2)
mhc_gemm() {
    extern __shared__ char smem[];
    const uint32_t sb = smem_u32(smem);
    const int t   = threadIdx.x;
    const int wid = t >> 5;
    const int n0   = blockIdx.x * BN;
    const int row0 = blockIdx.y * BM;
    const int wm0 = (wid & 3) * 32;   // warp tile rows
    const int wn0 = (wid >> 2) * 64;  // warp tile cols

    wmma::fragment<wmma::accumulator, 16, 16, 16, float> acc[2][4];
#pragma unroll
    for (int fm = 0; fm < 2; fm++)
#pragma unroll
        for (int fn = 0; fn < 4; fn++) wmma::fill_fragment(acc[fm][fn], 0.0f);

    const int r0c = t >> 2, c0c = (t & 3) * 16;
    const int r1c = 64 + r0c;

    auto issue = [&](int it) {
        if (it < NIT) {
            int s = it % NSTAGE;
            int p = it >> 4, kc = it & 15;
            const __nv_bfloat16* As = (p == 2) ? g_Alo : g_Ahi;
            const __nv_bfloat16* Ws = (p == 1) ? g_Wlo : g_Whi;
            const char* asrc = (const char*)(As + (size_t)row0 * FDIM + kc * BK);
            const char* wsrc = (const char*)(Ws + (size_t)n0 * FDIM + kc * BK);
            uint32_t adst = sb + s * STAGE_BYTES;
            uint32_t wdst = adst + 10240;
            cp16(adst + r0c * 80 + c0c, asrc + (size_t)r0c * 1024 + c0c);
            cp16(adst + r1c * 80 + c0c, asrc + (size_t)r1c * 1024 + c0c);
            cp16(wdst + r0c * 80 + c0c, wsrc + (size_t)r0c * 1024 + c0c);
            cp16(wdst + r1c * 80 + c0c, wsrc + (size_t)r1c * 1024 + c0c);
        }
        asm volatile("cp.async.commit_group;" ::: "memory");
    };

    issue(0);
    issue(1);
    for (int it = 0; it < NIT; ++it) {
        int s = it % NSTAGE;
        asm volatile("cp.async.wait_group 1;" ::: "memory");
        __syncthreads();

        const __nv_bfloat16* a_sm = (const __nv_bfloat16*)(smem + s * STAGE_BYTES);
        const __nv_bfloat16* w_sm = (const __nv_bfloat16*)(smem + s * STAGE_BYTES + 10240);
#pragma unroll
        for (int kk = 0; kk < BK; kk += 16) {
            wmma::fragment<wmma::matrix_a, 16, 16, 16, __nv_bfloat16, wmma::row_major> af[2];
            wmma::fragment<wmma::matrix_b, 16, 16, 16, __nv_bfloat16, wmma::col_major> bfr[4];
#pragma unroll
            for (int fm = 0; fm < 2; fm++)
                wmma::load_matrix_sync(af[fm], a_sm + (wm0 + fm * 16) * LDA + kk, LDA);
#pragma unroll
            for (int fn = 0; fn < 4; fn++)
                wmma::load_matrix_sync(bfr[fn], w_sm + (wn0 + fn * 16) * LDA + kk, LDA);
#pragma unroll
            for (int fm = 0; fm < 2; fm++)
#pragma unroll
                for (int fn = 0; fn < 4; fn++)
                    wmma::mma_sync(acc[fm][fn], af[fm], bfr[fn], acc[fm][fn]);
        }
        issue(it + 2);   // overwrites stage (it-1): all warps passed this iter's sync
    }

    // ---- epilogue: raw logits straight to scratch (bias/gprob applied in scatter) ----
    float* dst = g_scratch + (size_t)row0 * NCOLS + n0;
#pragma unroll
    for (int fm = 0; fm < 2; fm++)
#pragma unroll
        for (int fn = 0; fn < 4; fn++)
            wmma::store_matrix_sync(dst + (size_t)(wm0 + fm * 16) * NCOLS + wn0 + fn * 16,
                                    acc[fm][fn], NCOLS, wmma::mem_row_major);
}

// ---- scatter: (logit + bias) * gprob at tile load, then CSR gather -> out ----
__global__ void __launch_bounds__(512, 1)
mhc_scatter(const float* __restrict__ gprob,
            const float* __restrict__ bias,
            float* __restrict__ out) {
    extern __shared__ char smem[];
    float* wsm     = (float*)(smem + SC_WSM);
    int*   off_sm  = (int*)(smem + SC_OFF);
    int*   src_sm  = (int*)(smem + SC_SRC);
    float* gp_sm   = (float*)(smem + SC_GP);
    float* bias_sm = (float*)(smem + SC_BIAS);
    const int t = threadIdx.x;
    const int r0 = blockIdx.x * 32;

    for (int i = t; i <= NCLS; i += 512) off_sm[i] = g_cls_off[i];
    for (int i = t; i < NCOLS; i += 512) src_sm[i] = g_cls_src[i];
    for (int i = t; i < 32 * 16; i += 512) gp_sm[i] = gprob[(size_t)r0 * 16 + i];
    for (int i = t; i < NCOLS; i += 512) bias_sm[i] = bias[i];
    __syncthreads();

    // load 32x1024 tile, fusing bias + group-prob weighting
    const float4* src = (const float4*)(g_scratch + (size_t)r0 * NCOLS);
    for (int i = t; i < 32 * NCOLS / 4; i += 512) {
        int r = i >> 8;            // 256 float4 per row
        int n = (i & 255) * 4;
        float4 v = src[i];
        float gp = gp_sm[r * 16 + (n >> 6)];   // quad never crosses a 64-col boundary
        v.x = (v.x + bias_sm[n + 0]) * gp;
        v.y = (v.y + bias_sm[n + 1]) * gp;
        v.z = (v.z + bias_sm[n + 2]) * gp;
        v.w = (v.w + bias_sm[n + 3]) * gp;
        *(float4*)(wsm + i * 4) = v;
    }
    __syncthreads();

    for (int c = t; c < NCLS; c += 512) {
        int s0 = off_sm[c], s1 = off_sm[c + 1];
#pragma unroll 4
        for (int r = 0; r < 32; r++) {
            float s = 0.f;
            for (int k = s0; k < s1; k++) s += wsm[r * NCOLS + src_sm[k]];
            out[(size_t)(r0 + r) * NCLS + c] = s;
        }
    }
}

extern "C" void kernel_launch(void* const* d_in, const int* in_sizes, int n_in,
                              void* d_out, int out_size) {
    const float* features = (const float*)d_in[0];
    const float* gprob    = (const float*)d_in[1];
    const float* W        = (const float*)d_in[2];
    const float* bias     = (const float*)d_in[3];
    const int*   labels   = (const int*)d_in[4];
    float* out = (float*)d_out;

    static __nv_bfloat16 *hA, *lA, *hW, *lW;
    static bool init = false;
    if (!init) {
        cudaGetSymbolAddress((void**)&hA, g_Ahi);
        cudaGetSymbolAddress((void**)&lA, g_Alo);
        cudaGetSymbolAddress((void**)&hW, g_Whi);
        cudaGetSymbolAddress((void**)&lW, g_Wlo);
        cudaFuncSetAttribute(mhc_gemm, cudaFuncAttributeMaxDynamicSharedMemorySize, SMEM_GEMM);
        cudaFuncSetAttribute(mhc_scatter, cudaFuncAttributeMaxDynamicSharedMemorySize, SMEM_SCAT);
        init = true;
    }

    prep_kernel<<<1, 1024>>>(labels);
    prep_split<<<(B_ROWS * FDIM) / 1024, 256>>>(features, hA, lA);
    prep_split<<<(NCOLS * FDIM) / 1024, 256>>>(W, hW, lW);

    dim3 grid(NCOLS / BN, B_ROWS / BM);
    mhc_gemm<<<grid, 256, SMEM_GEMM>>>();
    mhc_scatter<<<B_ROWS / 32, 512, SMEM_SCAT>>>(gprob, bias, out);
}

// round 5
// speedup vs baseline: 1.5992x; 1.5992x over previous
#include <cuda_runtime.h>
#include <cuda_bf16.h>
#include <mma.h>
#include <cstdint>

using namespace nvcuda;

#define B_ROWS 32768
#define FDIM   512
#define NCOLS  1024
#define NCLS   1000

#define BM 128
#define BN 128
#define BK 64
#define LDA 72              // bf16 smem pitch (144B = 9*16B -> conflict-free LDSM)
#define LDE 136             // fp32 epilogue pitch
#define NIT 24              // 3 passes * (512/64)
#define STAGE_A 18432       // 128*144
#define STAGE_BYTES 36864   // A + W
#define SMEM_GEMM (2 * STAGE_BYTES)   // 73728 (>= 128*136*4 epilogue)

// scatter smem
#define SC_WSM 0
#define SC_OFF 131072
#define SC_SRC 135168
#define SMEM_SCAT 139264

// ---- device globals (legal scratch) ----
__device__ int   g_cls_off[NCLS + 1];
__device__ int   g_cls_src[NCOLS];
__device__ __nv_bfloat16 g_Ahi[(size_t)B_ROWS * FDIM];
__device__ __nv_bfloat16 g_Alo[(size_t)B_ROWS * FDIM];
__device__ __nv_bfloat16 g_Whi[NCOLS * FDIM];
__device__ __nv_bfloat16 g_Wlo[NCOLS * FDIM];
__device__ float g_scratch[(size_t)B_ROWS * NCOLS];

__device__ __forceinline__ uint32_t smem_u32(const void* p) {
    uint32_t a;
    asm("{ .reg .u64 t; cvta.to.shared.u64 t, %1; cvt.u32.u64 %0, t; }" : "=r"(a) : "l"(p));
    return a;
}
__device__ __forceinline__ void cp16(uint32_t dst, const void* src) {
    asm volatile("cp.async.cg.shared.global [%0], [%1], 16;" :: "r"(dst), "l"(src) : "memory");
}

// ---- prep: deterministic CSR of label_ids ----
__global__ void prep_kernel(const int* __restrict__ label_ids) {
    __shared__ int lab[NCOLS];
    __shared__ int cnt[NCLS];
    __shared__ int off[NCLS + 1];
    int t = threadIdx.x;
    lab[t] = label_ids[t];
    __syncthreads();
    if (t < NCLS) {
        int c = 0;
        for (int i = 0; i < NCOLS; i++) c += (lab[i] == t);
        cnt[t] = c;
    }
    __syncthreads();
    if (t == 0) {
        int acc = 0;
        for (int c = 0; c < NCLS; c++) { off[c] = acc; acc += cnt[c]; }
        off[NCLS] = acc;
    }
    __syncthreads();
    if (t <= NCLS) g_cls_off[t] = off[t];
    if (t < NCLS) {
        int pos = off[t];
        for (int i = 0; i < NCOLS; i++)
            if (lab[i] == t) g_cls_src[pos++] = i;
    }
}

// ---- prep: fp32 -> bf16 hi/lo ----
__global__ void prep_split(const float* __restrict__ src,
                           __nv_bfloat16* __restrict__ hi,
                           __nv_bfloat16* __restrict__ lo) {
    size_t i0 = ((size_t)blockIdx.x * 256 + threadIdx.x) * 4;
    float4 v = *(const float4*)(src + i0);
    __nv_bfloat16 h[4], l[4];
    float x;
    x = v.x; h[0] = __float2bfloat16_rn(x); l[0] = __float2bfloat16_rn(x - __bfloat162float(h[0]));
    x = v.y; h[1] = __float2bfloat16_rn(x); l[1] = __float2bfloat16_rn(x - __bfloat162float(h[1]));
    x = v.z; h[2] = __float2bfloat16_rn(x); l[2] = __float2bfloat16_rn(x - __bfloat162float(h[2]));
    x = v.w; h[3] = __float2bfloat16_rn(x); l[3] = __float2bfloat16_rn(x - __bfloat162float(h[3]));
    *(uint2*)(hi + i0) = *(uint2*)h;
    *(uint2*)(lo + i0) = *(uint2*)l;
}

// ---- GEMM: bf16 WMMA, 3-product split, BK=64 double-buffered cp.async ----
__global__ void __launch_bounds__(256, 2)
mhc_gemm(const float* __restrict__ gprob, const float* __restrict__ bias) {
    extern __shared__ char smem[];
    const uint32_t sb = smem_u32(smem);
    const int t   = threadIdx.x;
    const int wid = t >> 5;
    const int n0   = blockIdx.x * BN;
    const int row0 = blockIdx.y * BM;
    const int wm0 = (wid & 3) * 32;
    const int wn0 = (wid >> 2) * 64;

    wmma::fragment<wmma::accumulator, 16, 16, 16, float> acc[2][4];
#pragma unroll
    for (int fm = 0; fm < 2; fm++)
#pragma unroll
        for (int fn = 0; fn < 4; fn++) wmma::fill_fragment(acc[fm][fn], 0.0f);

    // 1024 16B-chunks per operand tile (128 rows x 8 chunks), 4 per thread
    auto issue = [&](int it, int s) {
        if (it < NIT) {
            int p = it >> 3, kc = it & 7;
            const __nv_bfloat16* As = (p == 2) ? g_Alo : g_Ahi;
            const __nv_bfloat16* Ws = (p == 1) ? g_Wlo : g_Whi;
            const char* asrc = (const char*)(As + (size_t)row0 * FDIM + kc * BK);
            const char* wsrc = (const char*)(Ws + (size_t)n0 * FDIM + kc * BK);
            uint32_t adst = sb + s * STAGE_BYTES;
            uint32_t wdst = adst + STAGE_A;
#pragma unroll
            for (int i = 0; i < 4; i++) {
                int id = i * 256 + t;
                int r = id >> 3, co = (id & 7) * 16;
                cp16(adst + r * 144 + co, asrc + (size_t)r * 1024 + co);
                cp16(wdst + r * 144 + co, wsrc + (size_t)r * 1024 + co);
            }
        }
        asm volatile("cp.async.commit_group;" ::: "memory");
    };

    issue(0, 0);
    for (int it = 0; it < NIT; ++it) {
        int s = it & 1;
        issue(it + 1, s ^ 1);
        asm volatile("cp.async.wait_group 1;" ::: "memory");
        __syncthreads();

        const __nv_bfloat16* a_sm = (const __nv_bfloat16*)(smem + s * STAGE_BYTES);
        const __nv_bfloat16* w_sm = (const __nv_bfloat16*)(smem + s * STAGE_BYTES + STAGE_A);
#pragma unroll
        for (int kk = 0; kk < BK; kk += 16) {
            wmma::fragment<wmma::matrix_a, 16, 16, 16, __nv_bfloat16, wmma::row_major> af[2];
            wmma::fragment<wmma::matrix_b, 16, 16, 16, __nv_bfloat16, wmma::col_major> bfr[4];
#pragma unroll
            for (int fm = 0; fm < 2; fm++)
                wmma::load_matrix_sync(af[fm], a_sm + (wm0 + fm * 16) * LDA + kk, LDA);
#pragma unroll
            for (int fn = 0; fn < 4; fn++)
                wmma::load_matrix_sync(bfr[fn], w_sm + (wn0 + fn * 16) * LDA + kk, LDA);
#pragma unroll
            for (int fm = 0; fm < 2; fm++)
#pragma unroll
                for (int fn = 0; fn < 4; fn++)
                    wmma::mma_sync(acc[fm][fn], af[fm], bfr[fn], acc[fm][fn]);
        }
        __syncthreads();
    }

    // ---- epilogue: frags -> smem -> (bias+gprob) -> scratch (coalesced f4) ----
    float* epi = (float*)smem;
#pragma unroll
    for (int fm = 0; fm < 2; fm++)
#pragma unroll
        for (int fn = 0; fn < 4; fn++)
            wmma::store_matrix_sync(epi + (wm0 + fm * 16) * LDE + wn0 + fn * 16,
                                    acc[fm][fn], LDE, wmma::mem_row_major);
    __syncthreads();

#pragma unroll
    for (int i = 0; i < 16; i++) {
        int idx = i * 256 + t;
        int r  = idx >> 5;
        int c4 = (idx & 31) * 4;
        float4 v = *(float4*)(epi + r * LDE + c4);
        int n = n0 + c4;
        float gp = __ldg(gprob + (size_t)(row0 + r) * 16 + (n >> 6));
        v.x = (v.x + __ldg(bias + n + 0)) * gp;
        v.y = (v.y + __ldg(bias + n + 1)) * gp;
        v.z = (v.z + __ldg(bias + n + 2)) * gp;
        v.w = (v.w + __ldg(bias + n + 3)) * gp;
        *(float4*)(g_scratch + (size_t)(row0 + r) * NCOLS + n) = v;
    }
}

// ---- scatter: CSR gather, row-outer/class-inner for coalesced stores ----
__global__ void __launch_bounds__(512, 1)
mhc_scatter(float* __restrict__ out) {
    extern __shared__ char smem[];
    float* wsm    = (float*)(smem + SC_WSM);
    int*   off_sm = (int*)(smem + SC_OFF);
    int*   src_sm = (int*)(smem + SC_SRC);
    const int t = threadIdx.x;
    const int r0 = blockIdx.x * 32;

    for (int i = t; i <= NCLS; i += 512) off_sm[i] = g_cls_off[i];
    for (int i = t; i < NCOLS; i += 512) src_sm[i] = g_cls_src[i];

    const float4* src = (const float4*)(g_scratch + (size_t)r0 * NCOLS);
    float4* dst4 = (float4*)wsm;
    for (int i = t; i < 32 * NCOLS / 4; i += 512) dst4[i] = src[i];
    __syncthreads();

#pragma unroll 2
    for (int r = 0; r < 32; r++) {
        const float* wrow = wsm + r * NCOLS;
        float* orow = out + (size_t)(r0 + r) * NCLS;
        for (int c = t; c < NCLS; c += 512) {
            int s0 = off_sm[c], s1 = off_sm[c + 1];
            float s = 0.f;
            for (int k = s0; k < s1; k++) s += wrow[src_sm[k]];
            orow[c] = s;                        // coalesced across threads
        }
    }
}

extern "C" void kernel_launch(void* const* d_in, const int* in_sizes, int n_in,
                              void* d_out, int out_size) {
    const float* features = (const float*)d_in[0];
    const float* gprob    = (const float*)d_in[1];
    const float* W        = (const float*)d_in[2];
    const float* bias     = (const float*)d_in[3];
    const int*   labels   = (const int*)d_in[4];
    float* out = (float*)d_out;

    static __nv_bfloat16 *hA, *lA, *hW, *lW;
    static bool init = false;
    if (!init) {
        cudaGetSymbolAddress((void**)&hA, g_Ahi);
        cudaGetSymbolAddress((void**)&lA, g_Alo);
        cudaGetSymbolAddress((void**)&hW, g_Whi);
        cudaGetSymbolAddress((void**)&lW, g_Wlo);
        cudaFuncSetAttribute(mhc_gemm, cudaFuncAttributeMaxDynamicSharedMemorySize, SMEM_GEMM);
        cudaFuncSetAttribute(mhc_scatter, cudaFuncAttributeMaxDynamicSharedMemorySize, SMEM_SCAT);
        init = true;
    }

    prep_kernel<<<1, 1024>>>(labels);
    prep_split<<<(B_ROWS * FDIM) / 1024, 256>>>(features, hA, lA);
    prep_split<<<(NCOLS * FDIM) / 1024, 256>>>(W, hW, lW);

    dim3 grid(NCOLS / BN, B_ROWS / BM);
    mhc_gemm<<<grid, 256, SMEM_GEMM>>>(gprob, bias);
    mhc_scatter<<<B_ROWS / 32, 512, SMEM_SCAT>>>(out);
}

// round 6
// speedup vs baseline: 1.6524x; 1.0333x over previous
#include <cuda_runtime.h>
#include <cuda_bf16.h>
#include <mma.h>
#include <cstdint>

using namespace nvcuda;

#define B_ROWS 32768
#define FDIM   512
#define NCOLS  1024
#define NCLS   1000

#define BM 128
#define BN 128
#define BK 32
#define LDA 40               // bf16 smem pitch (80B)
#define LDE 136              // fp32 epilogue pitch
#define NIT 16               // 512/32 (all 3 products per chunk)
#define TILE_B 10240         // one 128x32 bf16 tile @ pitch 80
#define STAGE_BYTES 40960    // Ahi+Alo+Whi+Wlo
#define SMEM_GEMM (2 * STAGE_BYTES)   // 81920 (>= 128*136*4 = 69632 epilogue)

// scatter smem
#define SC_WSM 0
#define SC_OFF 131072
#define SC_SRC 135168
#define SMEM_SCAT 139264

__device__ int   g_cls_off[NCLS + 1];
__device__ int   g_cls_src[NCOLS];
__device__ __nv_bfloat16 g_Ahi[(size_t)B_ROWS * FDIM];
__device__ __nv_bfloat16 g_Alo[(size_t)B_ROWS * FDIM];
__device__ __nv_bfloat16 g_Whi[NCOLS * FDIM];
__device__ __nv_bfloat16 g_Wlo[NCOLS * FDIM];
__device__ float g_scratch[(size_t)B_ROWS * NCOLS];

__device__ __forceinline__ uint32_t smem_u32(const void* p) {
    uint32_t a;
    asm("{ .reg .u64 t; cvta.to.shared.u64 t, %1; cvt.u32.u64 %0, t; }" : "=r"(a) : "l"(p));
    return a;
}
__device__ __forceinline__ void cp16(uint32_t dst, const void* src) {
    asm volatile("cp.async.cg.shared.global [%0], [%1], 16;" :: "r"(dst), "l"(src) : "memory");
}

// ---- prep: deterministic CSR of label_ids ----
__global__ void prep_kernel(const int* __restrict__ label_ids) {
    __shared__ int lab[NCOLS];
    __shared__ int cnt[NCLS];
    __shared__ int off[NCLS + 1];
    int t = threadIdx.x;
    lab[t] = label_ids[t];
    __syncthreads();
    if (t < NCLS) {
        int c = 0;
        for (int i = 0; i < NCOLS; i++) c += (lab[i] == t);
        cnt[t] = c;
    }
    __syncthreads();
    if (t == 0) {
        int acc = 0;
        for (int c = 0; c < NCLS; c++) { off[c] = acc; acc += cnt[c]; }
        off[NCLS] = acc;
    }
    __syncthreads();
    if (t <= NCLS) g_cls_off[t] = off[t];
    if (t < NCLS) {
        int pos = off[t];
        for (int i = 0; i < NCOLS; i++)
            if (lab[i] == t) g_cls_src[pos++] = i;
    }
}

// ---- prep: fp32 -> bf16 hi/lo for A and W in one launch ----
#define A_BLOCKS ((B_ROWS * FDIM) / 1024)
__global__ void prep_split(const float* __restrict__ A, const float* __restrict__ W,
                           __nv_bfloat16* __restrict__ Ahi, __nv_bfloat16* __restrict__ Alo,
                           __nv_bfloat16* __restrict__ Whi, __nv_bfloat16* __restrict__ Wlo) {
    int blk = blockIdx.x;
    const float* src;
    __nv_bfloat16 *hi, *lo;
    size_t i0;
    if (blk < A_BLOCKS) {
        src = A; hi = Ahi; lo = Alo;
        i0 = ((size_t)blk * 256 + threadIdx.x) * 4;
    } else {
        src = W; hi = Whi; lo = Wlo;
        i0 = ((size_t)(blk - A_BLOCKS) * 256 + threadIdx.x) * 4;
    }
    float4 v = *(const float4*)(src + i0);
    __nv_bfloat16 h[4], l[4];
    float x;
    x = v.x; h[0] = __float2bfloat16_rn(x); l[0] = __float2bfloat16_rn(x - __bfloat162float(h[0]));
    x = v.y; h[1] = __float2bfloat16_rn(x); l[1] = __float2bfloat16_rn(x - __bfloat162float(h[1]));
    x = v.z; h[2] = __float2bfloat16_rn(x); l[2] = __float2bfloat16_rn(x - __bfloat162float(h[2]));
    x = v.w; h[3] = __float2bfloat16_rn(x); l[3] = __float2bfloat16_rn(x - __bfloat162float(h[3]));
    *(uint2*)(hi + i0) = *(uint2*)h;
    *(uint2*)(lo + i0) = *(uint2*)l;
}

// ---- GEMM: fused 3-product split per K-chunk, double-buffered cp.async ----
__global__ void __launch_bounds__(256, 2)
mhc_gemm(const float* __restrict__ gprob, const float* __restrict__ bias) {
    extern __shared__ char smem[];
    const uint32_t sb = smem_u32(smem);
    const int t   = threadIdx.x;
    const int wid = t >> 5;
    const int n0   = blockIdx.x * BN;
    const int row0 = blockIdx.y * BM;
    const int wm0 = (wid & 3) * 32;
    const int wn0 = (wid >> 2) * 64;

    wmma::fragment<wmma::accumulator, 16, 16, 16, float> acc[2][4];
#pragma unroll
    for (int fm = 0; fm < 2; fm++)
#pragma unroll
        for (int fn = 0; fn < 4; fn++) wmma::fill_fragment(acc[fm][fn], 0.0f);

    // per stage: 4 tiles x 512 16B-chunks; 256 threads -> 2 chunks/tile/thread
    auto issue = [&](int it, int s) {
        if (it < NIT) {
            const char* ah = (const char*)(g_Ahi + (size_t)row0 * FDIM + it * BK);
            const char* al = (const char*)(g_Alo + (size_t)row0 * FDIM + it * BK);
            const char* wh = (const char*)(g_Whi + (size_t)n0 * FDIM + it * BK);
            const char* wl = (const char*)(g_Wlo + (size_t)n0 * FDIM + it * BK);
            uint32_t st = sb + s * STAGE_BYTES;
#pragma unroll
            for (int i = 0; i < 2; i++) {
                int id = i * 256 + t;
                int r = id >> 2, co = (id & 3) * 16;
                size_t go = (size_t)r * 1024 + co;
                uint32_t so = r * 80 + co;
                cp16(st + so,              ah + go);
                cp16(st + TILE_B + so,     al + go);
                cp16(st + 2 * TILE_B + so, wh + go);
                cp16(st + 3 * TILE_B + so, wl + go);
            }
        }
        asm volatile("cp.async.commit_group;" ::: "memory");
    };

    issue(0, 0);
    for (int it = 0; it < NIT; ++it) {
        int s = it & 1;
        issue(it + 1, s ^ 1);
        asm volatile("cp.async.wait_group 1;" ::: "memory");
        __syncthreads();

        const __nv_bfloat16* ah_sm = (const __nv_bfloat16*)(smem + s * STAGE_BYTES);
        const __nv_bfloat16* al_sm = (const __nv_bfloat16*)(smem + s * STAGE_BYTES + TILE_B);
        const __nv_bfloat16* wh_sm = (const __nv_bfloat16*)(smem + s * STAGE_BYTES + 2 * TILE_B);
        const __nv_bfloat16* wl_sm = (const __nv_bfloat16*)(smem + s * STAGE_BYTES + 3 * TILE_B);
#pragma unroll
        for (int kk = 0; kk < BK; kk += 16) {
            wmma::fragment<wmma::matrix_a, 16, 16, 16, __nv_bfloat16, wmma::row_major> afh[2], afl[2];
            wmma::fragment<wmma::matrix_b, 16, 16, 16, __nv_bfloat16, wmma::col_major> bfh[4], bfl[4];
#pragma unroll
            for (int fm = 0; fm < 2; fm++)
                wmma::load_matrix_sync(afh[fm], ah_sm + (wm0 + fm * 16) * LDA + kk, LDA);
#pragma unroll
            for (int fn = 0; fn < 4; fn++)
                wmma::load_matrix_sync(bfh[fn], wh_sm + (wn0 + fn * 16) * LDA + kk, LDA);
            // hh
#pragma unroll
            for (int fm = 0; fm < 2; fm++)
#pragma unroll
                for (int fn = 0; fn < 4; fn++)
                    wmma::mma_sync(acc[fm][fn], afh[fm], bfh[fn], acc[fm][fn]);
            // lh: Alo x Whi (reuse bfh)
#pragma unroll
            for (int fm = 0; fm < 2; fm++)
                wmma::load_matrix_sync(afl[fm], al_sm + (wm0 + fm * 16) * LDA + kk, LDA);
#pragma unroll
            for (int fm = 0; fm < 2; fm++)
#pragma unroll
                for (int fn = 0; fn < 4; fn++)
                    wmma::mma_sync(acc[fm][fn], afl[fm], bfh[fn], acc[fm][fn]);
            // hl: Ahi x Wlo (reuse afh)
#pragma unroll
            for (int fn = 0; fn < 4; fn++)
                wmma::load_matrix_sync(bfl[fn], wl_sm + (wn0 + fn * 16) * LDA + kk, LDA);
#pragma unroll
            for (int fm = 0; fm < 2; fm++)
#pragma unroll
                for (int fn = 0; fn < 4; fn++)
                    wmma::mma_sync(acc[fm][fn], afh[fm], bfl[fn], acc[fm][fn]);
        }
        __syncthreads();
    }

    // ---- epilogue: frags -> smem -> (bias+gprob) -> scratch (coalesced f4) ----
    float* epi = (float*)smem;
#pragma unroll
    for (int fm = 0; fm < 2; fm++)
#pragma unroll
        for (int fn = 0; fn < 4; fn++)
            wmma::store_matrix_sync(epi + (wm0 + fm * 16) * LDE + wn0 + fn * 16,
                                    acc[fm][fn], LDE, wmma::mem_row_major);
    __syncthreads();

#pragma unroll
    for (int i = 0; i < 16; i++) {
        int idx = i * 256 + t;
        int r  = idx >> 5;
        int c4 = (idx & 31) * 4;
        float4 v = *(float4*)(epi + r * LDE + c4);
        int n = n0 + c4;
        float gp = __ldg(gprob + (size_t)(row0 + r) * 16 + (n >> 6));
        v.x = (v.x + __ldg(bias + n + 0)) * gp;
        v.y = (v.y + __ldg(bias + n + 1)) * gp;
        v.z = (v.z + __ldg(bias + n + 2)) * gp;
        v.w = (v.w + __ldg(bias + n + 3)) * gp;
        *(float4*)(g_scratch + (size_t)(row0 + r) * NCOLS + n) = v;
    }
}

// ---- scatter: CSR gather, row-outer/class-inner, coalesced stores ----
__global__ void __launch_bounds__(512, 1)
mhc_scatter(float* __restrict__ out) {
    extern __shared__ char smem[];
    float* wsm    = (float*)(smem + SC_WSM);
    int*   off_sm = (int*)(smem + SC_OFF);
    int*   src_sm = (int*)(smem + SC_SRC);
    const int t = threadIdx.x;
    const int r0 = blockIdx.x * 32;

    for (int i = t; i <= NCLS; i += 512) off_sm[i] = g_cls_off[i];
    for (int i = t; i < NCOLS; i += 512) src_sm[i] = g_cls_src[i];

    const float4* src = (const float4*)(g_scratch + (size_t)r0 * NCOLS);
    float4* dst4 = (float4*)wsm;
    for (int i = t; i < 32 * NCOLS / 4; i += 512) dst4[i] = src[i];
    __syncthreads();

#pragma unroll 2
    for (int r = 0; r < 32; r++) {
        const float* wrow = wsm + r * NCOLS;
        float* orow = out + (size_t)(r0 + r) * NCLS;
        for (int c = t; c < NCLS; c += 512) {
            int s0 = off_sm[c], s1 = off_sm[c + 1];
            float s = 0.f;
            for (int k = s0; k < s1; k++) s += wrow[src_sm[k]];
            orow[c] = s;
        }
    }
}

extern "C" void kernel_launch(void* const* d_in, const int* in_sizes, int n_in,
                              void* d_out, int out_size) {
    const float* features = (const float*)d_in[0];
    const float* gprob    = (const float*)d_in[1];
    const float* W        = (const float*)d_in[2];
    const float* bias     = (const float*)d_in[3];
    const int*   labels   = (const int*)d_in[4];
    float* out = (float*)d_out;

    static __nv_bfloat16 *hA, *lA, *hW, *lW;
    static bool init = false;
    if (!init) {
        cudaGetSymbolAddress((void**)&hA, g_Ahi);
        cudaGetSymbolAddress((void**)&lA, g_Alo);
        cudaGetSymbolAddress((void**)&hW, g_Whi);
        cudaGetSymbolAddress((void**)&lW, g_Wlo);
        cudaFuncSetAttribute(mhc_gemm, cudaFuncAttributeMaxDynamicSharedMemorySize, SMEM_GEMM);
        cudaFuncSetAttribute(mhc_scatter, cudaFuncAttributeMaxDynamicSharedMemorySize, SMEM_SCAT);
        init = true;
    }

    prep_kernel<<<1, 1024>>>(labels);
    prep_split<<<A_BLOCKS + (NCOLS * FDIM) / 1024, 256>>>(features, W, hA, lA, hW, lW);

    dim3 grid(NCOLS / BN, B_ROWS / BM);
    mhc_gemm<<<grid, 256, SMEM_GEMM>>>(gprob, bias);
    mhc_scatter<<<B_ROWS / 32, 512, SMEM_SCAT>>>(out);
}

// round 7
// speedup vs baseline: 1.8746x; 1.1344x over previous
#include <cuda_runtime.h>
#include <cuda_bf16.h>
#include <mma.h>
#include <cstdint>

using namespace nvcuda;

#define B_ROWS 32768
#define FDIM   512
#define NCOLS  1024
#define NCLS   1000

#define BM 128
#define BN 128
#define BK 32
#define LDA 40               // bf16 smem pitch (80B)
#define LDE 136              // fp32 epilogue pitch
#define NIT 16               // 512/32 (all 3 products per chunk)
#define TILE_B 10240         // one 128x32 bf16 tile @ pitch 80
#define STAGE_BYTES 40960    // Ahi+Alo+Whi+Wlo
#define SMEM_GEMM (2 * STAGE_BYTES)   // 81920 (>= 128*136*4 = 69632 epilogue)

// scatter: 16-row tile -> 3 CTAs/SM
#define SROWS 16
#define SC_WSM 0                        // [16][1024] f = 65536B
#define SC_OFF 65536                    // int[1001]
#define SC_SRC 69640                    // int[1024]  (69640 = 65536+4104, 8B aligned)
#define SMEM_SCAT 73736

__device__ int   g_cls_off[NCLS + 1];
__device__ int   g_cls_src[NCOLS];
__device__ __nv_bfloat16 g_Ahi[(size_t)B_ROWS * FDIM];
__device__ __nv_bfloat16 g_Alo[(size_t)B_ROWS * FDIM];
__device__ __nv_bfloat16 g_Whi[NCOLS * FDIM];
__device__ __nv_bfloat16 g_Wlo[NCOLS * FDIM];
__device__ float g_scratch[(size_t)B_ROWS * NCOLS];

__device__ __forceinline__ uint32_t smem_u32(const void* p) {
    uint32_t a;
    asm("{ .reg .u64 t; cvta.to.shared.u64 t, %1; cvt.u32.u64 %0, t; }" : "=r"(a) : "l"(p));
    return a;
}
__device__ __forceinline__ void cp16(uint32_t dst, const void* src) {
    asm volatile("cp.async.cg.shared.global [%0], [%1], 16;" :: "r"(dst), "l"(src) : "memory");
}

// ---- prep: deterministic CSR of label_ids ----
__global__ void prep_kernel(const int* __restrict__ label_ids) {
    __shared__ int lab[NCOLS];
    __shared__ int cnt[NCLS];
    __shared__ int off[NCLS + 1];
    int t = threadIdx.x;
    lab[t] = label_ids[t];
    __syncthreads();
    if (t < NCLS) {
        int c = 0;
        for (int i = 0; i < NCOLS; i++) c += (lab[i] == t);
        cnt[t] = c;
    }
    __syncthreads();
    if (t == 0) {
        int acc = 0;
        for (int c = 0; c < NCLS; c++) { off[c] = acc; acc += cnt[c]; }
        off[NCLS] = acc;
    }
    __syncthreads();
    if (t <= NCLS) g_cls_off[t] = off[t];
    if (t < NCLS) {
        int pos = off[t];
        for (int i = 0; i < NCOLS; i++)
            if (lab[i] == t) g_cls_src[pos++] = i;
    }
}

// ---- prep: fp32 -> bf16 hi/lo for A and W in one launch ----
#define A_BLOCKS ((B_ROWS * FDIM) / 1024)
__global__ void prep_split(const float* __restrict__ A, const float* __restrict__ W,
                           __nv_bfloat16* __restrict__ Ahi, __nv_bfloat16* __restrict__ Alo,
                           __nv_bfloat16* __restrict__ Whi, __nv_bfloat16* __restrict__ Wlo) {
    int blk = blockIdx.x;
    const float* src;
    __nv_bfloat16 *hi, *lo;
    size_t i0;
    if (blk < A_BLOCKS) {
        src = A; hi = Ahi; lo = Alo;
        i0 = ((size_t)blk * 256 + threadIdx.x) * 4;
    } else {
        src = W; hi = Whi; lo = Wlo;
        i0 = ((size_t)(blk - A_BLOCKS) * 256 + threadIdx.x) * 4;
    }
    float4 v = *(const float4*)(src + i0);
    __nv_bfloat16 h[4], l[4];
    float x;
    x = v.x; h[0] = __float2bfloat16_rn(x); l[0] = __float2bfloat16_rn(x - __bfloat162float(h[0]));
    x = v.y; h[1] = __float2bfloat16_rn(x); l[1] = __float2bfloat16_rn(x - __bfloat162float(h[1]));
    x = v.z; h[2] = __float2bfloat16_rn(x); l[2] = __float2bfloat16_rn(x - __bfloat162float(h[2]));
    x = v.w; h[3] = __float2bfloat16_rn(x); l[3] = __float2bfloat16_rn(x - __bfloat162float(h[3]));
    *(uint2*)(hi + i0) = *(uint2*)h;
    *(uint2*)(lo + i0) = *(uint2*)l;
}

// ---- GEMM: fused 3-product split per K-chunk, double-buffered cp.async ----
__global__ void __launch_bounds__(256, 2)
mhc_gemm(const float* __restrict__ gprob, const float* __restrict__ bias) {
    extern __shared__ char smem[];
    const uint32_t sb = smem_u32(smem);
    const int t   = threadIdx.x;
    const int wid = t >> 5;
    const int n0   = blockIdx.x * BN;
    const int row0 = blockIdx.y * BM;
    const int wm0 = (wid & 3) * 32;
    const int wn0 = (wid >> 2) * 64;

    wmma::fragment<wmma::accumulator, 16, 16, 16, float> acc[2][4];
#pragma unroll
    for (int fm = 0; fm < 2; fm++)
#pragma unroll
        for (int fn = 0; fn < 4; fn++) wmma::fill_fragment(acc[fm][fn], 0.0f);

    auto issue = [&](int it, int s) {
        if (it < NIT) {
            const char* ah = (const char*)(g_Ahi + (size_t)row0 * FDIM + it * BK);
            const char* al = (const char*)(g_Alo + (size_t)row0 * FDIM + it * BK);
            const char* wh = (const char*)(g_Whi + (size_t)n0 * FDIM + it * BK);
            const char* wl = (const char*)(g_Wlo + (size_t)n0 * FDIM + it * BK);
            uint32_t st = sb + s * STAGE_BYTES;
#pragma unroll
            for (int i = 0; i < 2; i++) {
                int id = i * 256 + t;
                int r = id >> 2, co = (id & 3) * 16;
                size_t go = (size_t)r * 1024 + co;
                uint32_t so = r * 80 + co;
                cp16(st + so,              ah + go);
                cp16(st + TILE_B + so,     al + go);
                cp16(st + 2 * TILE_B + so, wh + go);
                cp16(st + 3 * TILE_B + so, wl + go);
            }
        }
        asm volatile("cp.async.commit_group;" ::: "memory");
    };

    issue(0, 0);
    for (int it = 0; it < NIT; ++it) {
        int s = it & 1;
        issue(it + 1, s ^ 1);
        asm volatile("cp.async.wait_group 1;" ::: "memory");
        __syncthreads();

        const __nv_bfloat16* ah_sm = (const __nv_bfloat16*)(smem + s * STAGE_BYTES);
        const __nv_bfloat16* al_sm = (const __nv_bfloat16*)(smem + s * STAGE_BYTES + TILE_B);
        const __nv_bfloat16* wh_sm = (const __nv_bfloat16*)(smem + s * STAGE_BYTES + 2 * TILE_B);
        const __nv_bfloat16* wl_sm = (const __nv_bfloat16*)(smem + s * STAGE_BYTES + 3 * TILE_B);
#pragma unroll
        for (int kk = 0; kk < BK; kk += 16) {
            wmma::fragment<wmma::matrix_a, 16, 16, 16, __nv_bfloat16, wmma::row_major> afh[2], afl[2];
            wmma::fragment<wmma::matrix_b, 16, 16, 16, __nv_bfloat16, wmma::col_major> bfh[4], bfl[4];
#pragma unroll
            for (int fm = 0; fm < 2; fm++)
                wmma::load_matrix_sync(afh[fm], ah_sm + (wm0 + fm * 16) * LDA + kk, LDA);
#pragma unroll
            for (int fn = 0; fn < 4; fn++)
                wmma::load_matrix_sync(bfh[fn], wh_sm + (wn0 + fn * 16) * LDA + kk, LDA);
#pragma unroll
            for (int fm = 0; fm < 2; fm++)
#pragma unroll
                for (int fn = 0; fn < 4; fn++)
                    wmma::mma_sync(acc[fm][fn], afh[fm], bfh[fn], acc[fm][fn]);
#pragma unroll
            for (int fm = 0; fm < 2; fm++)
                wmma::load_matrix_sync(afl[fm], al_sm + (wm0 + fm * 16) * LDA + kk, LDA);
#pragma unroll
            for (int fm = 0; fm < 2; fm++)
#pragma unroll
                for (int fn = 0; fn < 4; fn++)
                    wmma::mma_sync(acc[fm][fn], afl[fm], bfh[fn], acc[fm][fn]);
#pragma unroll
            for (int fn = 0; fn < 4; fn++)
                wmma::load_matrix_sync(bfl[fn], wl_sm + (wn0 + fn * 16) * LDA + kk, LDA);
#pragma unroll
            for (int fm = 0; fm < 2; fm++)
#pragma unroll
                for (int fn = 0; fn < 4; fn++)
                    wmma::mma_sync(acc[fm][fn], afh[fm], bfl[fn], acc[fm][fn]);
        }
        __syncthreads();
    }

    // ---- epilogue: frags -> smem -> (bias+gprob) -> scratch (coalesced f4) ----
    float* epi = (float*)smem;
#pragma unroll
    for (int fm = 0; fm < 2; fm++)
#pragma unroll
        for (int fn = 0; fn < 4; fn++)
            wmma::store_matrix_sync(epi + (wm0 + fm * 16) * LDE + wn0 + fn * 16,
                                    acc[fm][fn], LDE, wmma::mem_row_major);
    __syncthreads();

#pragma unroll
    for (int i = 0; i < 16; i++) {
        int idx = i * 256 + t;
        int r  = idx >> 5;
        int c4 = (idx & 31) * 4;
        float4 v = *(float4*)(epi + r * LDE + c4);
        int n = n0 + c4;
        float gp = __ldg(gprob + (size_t)(row0 + r) * 16 + (n >> 6));
        v.x = (v.x + __ldg(bias + n + 0)) * gp;
        v.y = (v.y + __ldg(bias + n + 1)) * gp;
        v.z = (v.z + __ldg(bias + n + 2)) * gp;
        v.w = (v.w + __ldg(bias + n + 3)) * gp;
        *(float4*)(g_scratch + (size_t)(row0 + r) * NCOLS + n) = v;
    }
}

// ---- scatter: 16-row tiles, 3 CTAs/SM, class-outer/row-inner gather ----
__global__ void __launch_bounds__(256, 3)
mhc_scatter(float* __restrict__ out) {
    extern __shared__ char smem[];
    float* wsm    = (float*)(smem + SC_WSM);
    int*   off_sm = (int*)(smem + SC_OFF);
    int*   src_sm = (int*)(smem + SC_SRC);
    const int t = threadIdx.x;
    const int r0 = blockIdx.x * SROWS;

    for (int i = t; i <= NCLS; i += 256) off_sm[i] = g_cls_off[i];
    for (int i = t; i < NCOLS; i += 256) src_sm[i] = g_cls_src[i];

    const float4* src = (const float4*)(g_scratch + (size_t)r0 * NCOLS);
    float4* dst4 = (float4*)wsm;
#pragma unroll
    for (int i = 0; i < SROWS * NCOLS / 4 / 256; i++)
        dst4[i * 256 + t] = src[i * 256 + t];
    __syncthreads();

    // class-outer (per thread), rows inner: off/src loaded once per class
    for (int c = t; c < NCLS; c += 256) {
        int s0 = off_sm[c], s1 = off_sm[c + 1];
        float* ocol = out + (size_t)r0 * NCLS + c;
        if (s1 == s0) {
#pragma unroll
            for (int r = 0; r < SROWS; r++) ocol[(size_t)r * NCLS] = 0.f;
        } else if (s1 == s0 + 1) {
            int src0 = src_sm[s0];
#pragma unroll
            for (int r = 0; r < SROWS; r++)
                ocol[(size_t)r * NCLS] = wsm[r * NCOLS + src0];
        } else {
#pragma unroll
            for (int r = 0; r < SROWS; r++) {
                float s = 0.f;
                for (int k = s0; k < s1; k++) s += wsm[r * NCOLS + src_sm[k]];
                ocol[(size_t)r * NCLS] = s;
            }
        }
    }
}

extern "C" void kernel_launch(void* const* d_in, const int* in_sizes, int n_in,
                              void* d_out, int out_size) {
    const float* features = (const float*)d_in[0];
    const float* gprob    = (const float*)d_in[1];
    const float* W        = (const float*)d_in[2];
    const float* bias     = (const float*)d_in[3];
    const int*   labels   = (const int*)d_in[4];
    float* out = (float*)d_out;

    static __nv_bfloat16 *hA, *lA, *hW, *lW;
    static bool init = false;
    if (!init) {
        cudaGetSymbolAddress((void**)&hA, g_Ahi);
        cudaGetSymbolAddress((void**)&lA, g_Alo);
        cudaGetSymbolAddress((void**)&hW, g_Whi);
        cudaGetSymbolAddress((void**)&lW, g_Wlo);
        cudaFuncSetAttribute(mhc_gemm, cudaFuncAttributeMaxDynamicSharedMemorySize, SMEM_GEMM);
        cudaFuncSetAttribute(mhc_scatter, cudaFuncAttributeMaxDynamicSharedMemorySize, SMEM_SCAT);
        init = true;
    }

    prep_kernel<<<1, 1024>>>(labels);
    prep_split<<<A_BLOCKS + (NCOLS * FDIM) / 1024, 256>>>(features, W, hA, lA, hW, lW);

    dim3 grid(NCOLS / BN, B_ROWS / BM);
    mhc_gemm<<<grid, 256, SMEM_GEMM>>>(gprob, bias);
    mhc_scatter<<<B_ROWS / SROWS, 256, SMEM_SCAT>>>(out);
}

// round 9
// speedup vs baseline: 1.9985x; 1.0661x over previous
#include <cuda_runtime.h>
#include <cuda_bf16.h>
#include <mma.h>
#include <cstdint>

using namespace nvcuda;

#define B_ROWS 32768
#define FDIM   512
#define NCOLS  1024
#define NCLS   1000

#define BM 128
#define BN 128
#define BK 32
#define LDA 40               // bf16 smem pitch (80B)
#define LDE 136              // fp32 epilogue pitch
#define NIT 16               // 512/32 (all 3 products per chunk)
#define TILE_B 10240         // one 128x32 bf16 tile @ pitch 80
#define STAGE_BYTES 40960    // Ahi+Alo+Whi+Wlo
#define SMEM_GEMM (2 * STAGE_BYTES)   // 81920 (>= 128*136*4 = 69632 epilogue)

// scatter: 8-row tile -> 4 CTAs/SM
#define SROWS 8
#define SC_WSM 0                        // [8][1024] f = 32768B
#define SC_OFF 32768                    // int[1001]
#define SC_SRC 36872                    // int[1024]
#define SMEM_SCAT 40968

__device__ int   g_cls_off[NCLS + 1];
__device__ int   g_cls_src[NCOLS];
__device__ __nv_bfloat16 g_Ahi[(size_t)B_ROWS * FDIM];
__device__ __nv_bfloat16 g_Alo[(size_t)B_ROWS * FDIM];
__device__ __nv_bfloat16 g_Whi[NCOLS * FDIM];
__device__ __nv_bfloat16 g_Wlo[NCOLS * FDIM];
__device__ float g_scratch[(size_t)B_ROWS * NCOLS];

__device__ __forceinline__ uint32_t smem_u32(const void* p) {
    uint32_t a;
    asm("{ .reg .u64 t; cvta.to.shared.u64 t, %1; cvt.u32.u64 %0, t; }" : "=r"(a) : "l"(p));
    return a;
}
__device__ __forceinline__ void cp16(uint32_t dst, const void* src) {
    asm volatile("cp.async.cg.shared.global [%0], [%1], 16;" :: "r"(dst), "l"(src) : "memory");
}

// ---- prep: deterministic CSR of label_ids ----
__global__ void prep_kernel(const int* __restrict__ label_ids) {
    __shared__ int lab[NCOLS];
    __shared__ int cnt[NCLS];
    __shared__ int off[NCLS + 1];
    int t = threadIdx.x;
    lab[t] = label_ids[t];
    __syncthreads();
    if (t < NCLS) {
        int c = 0;
        for (int i = 0; i < NCOLS; i++) c += (lab[i] == t);
        cnt[t] = c;
    }
    __syncthreads();
    if (t == 0) {
        int acc = 0;
        for (int c = 0; c < NCLS; c++) { off[c] = acc; acc += cnt[c]; }
        off[NCLS] = acc;
    }
    __syncthreads();
    if (t <= NCLS) g_cls_off[t] = off[t];
    if (t < NCLS) {
        int pos = off[t];
        for (int i = 0; i < NCOLS; i++)
            if (lab[i] == t) g_cls_src[pos++] = i;
    }
}

// ---- prep: fp32 -> bf16 hi/lo for A and W in one launch ----
#define A_BLOCKS ((B_ROWS * FDIM) / 1024)
__global__ void prep_split(const float* __restrict__ A, const float* __restrict__ W,
                           __nv_bfloat16* __restrict__ Ahi, __nv_bfloat16* __restrict__ Alo,
                           __nv_bfloat16* __restrict__ Whi, __nv_bfloat16* __restrict__ Wlo) {
    int blk = blockIdx.x;
    const float* src;
    __nv_bfloat16 *hi, *lo;
    size_t i0;
    if (blk < A_BLOCKS) {
        src = A; hi = Ahi; lo = Alo;
        i0 = ((size_t)blk * 256 + threadIdx.x) * 4;
    } else {
        src = W; hi = Whi; lo = Wlo;
        i0 = ((size_t)(blk - A_BLOCKS) * 256 + threadIdx.x) * 4;
    }
    float4 v = *(const float4*)(src + i0);
    __nv_bfloat16 h[4], l[4];
    float x;
    x = v.x; h[0] = __float2bfloat16_rn(x); l[0] = __float2bfloat16_rn(x - __bfloat162float(h[0]));
    x = v.y; h[1] = __float2bfloat16_rn(x); l[1] = __float2bfloat16_rn(x - __bfloat162float(h[1]));
    x = v.z; h[2] = __float2bfloat16_rn(x); l[2] = __float2bfloat16_rn(x - __bfloat162float(h[2]));
    x = v.w; h[3] = __float2bfloat16_rn(x); l[3] = __float2bfloat16_rn(x - __bfloat162float(h[3]));
    *(uint2*)(hi + i0) = *(uint2*)h;
    *(uint2*)(lo + i0) = *(uint2*)l;
}

// ---- GEMM: fused 3-product split, double-buffered cp.async (proven R7 schedule) ----
__global__ void __launch_bounds__(256, 2)
mhc_gemm(const float* __restrict__ gprob, const float* __restrict__ bias) {
    extern __shared__ char smem[];
    const uint32_t sb = smem_u32(smem);
    const int t   = threadIdx.x;
    const int wid = t >> 5;
    const int n0   = blockIdx.x * BN;
    const int row0 = blockIdx.y * BM;
    const int wm0 = (wid & 3) * 32;
    const int wn0 = (wid >> 2) * 64;

    wmma::fragment<wmma::accumulator, 16, 16, 16, float> acc[2][4];
#pragma unroll
    for (int fm = 0; fm < 2; fm++)
#pragma unroll
        for (int fn = 0; fn < 4; fn++) wmma::fill_fragment(acc[fm][fn], 0.0f);

    auto issue = [&](int it, int s) {
        if (it < NIT) {
            const char* ah = (const char*)(g_Ahi + (size_t)row0 * FDIM + it * BK);
            const char* al = (const char*)(g_Alo + (size_t)row0 * FDIM + it * BK);
            const char* wh = (const char*)(g_Whi + (size_t)n0 * FDIM + it * BK);
            const char* wl = (const char*)(g_Wlo + (size_t)n0 * FDIM + it * BK);
            uint32_t st = sb + s * STAGE_BYTES;
#pragma unroll
            for (int i = 0; i < 2; i++) {
                int id = i * 256 + t;
                int r = id >> 2, co = (id & 3) * 16;
                size_t go = (size_t)r * 1024 + co;
                uint32_t so = r * 80 + co;
                cp16(st + so,              ah + go);
                cp16(st + TILE_B + so,     al + go);
                cp16(st + 2 * TILE_B + so, wh + go);
                cp16(st + 3 * TILE_B + so, wl + go);
            }
        }
        asm volatile("cp.async.commit_group;" ::: "memory");
    };

    issue(0, 0);
    for (int it = 0; it < NIT; ++it) {
        int s = it & 1;
        issue(it + 1, s ^ 1);            // stage s^1 free: trailing sync of iter it-1
        asm volatile("cp.async.wait_group 1;" ::: "memory");
        __syncthreads();                 // collective: ALL threads' stage-s copies landed

        const __nv_bfloat16* ah_sm = (const __nv_bfloat16*)(smem + s * STAGE_BYTES);
        const __nv_bfloat16* al_sm = (const __nv_bfloat16*)(smem + s * STAGE_BYTES + TILE_B);
        const __nv_bfloat16* wh_sm = (const __nv_bfloat16*)(smem + s * STAGE_BYTES + 2 * TILE_B);
        const __nv_bfloat16* wl_sm = (const __nv_bfloat16*)(smem + s * STAGE_BYTES + 3 * TILE_B);
#pragma unroll
        for (int kk = 0; kk < BK; kk += 16) {
            wmma::fragment<wmma::matrix_a, 16, 16, 16, __nv_bfloat16, wmma::row_major> afh[2], afl[2];
            wmma::fragment<wmma::matrix_b, 16, 16, 16, __nv_bfloat16, wmma::col_major> bfh[4], bfl[4];
#pragma unroll
            for (int fm = 0; fm < 2; fm++)
                wmma::load_matrix_sync(afh[fm], ah_sm + (wm0 + fm * 16) * LDA + kk, LDA);
#pragma unroll
            for (int fn = 0; fn < 4; fn++)
                wmma::load_matrix_sync(bfh[fn], wh_sm + (wn0 + fn * 16) * LDA + kk, LDA);
#pragma unroll
            for (int fm = 0; fm < 2; fm++)
#pragma unroll
                for (int fn = 0; fn < 4; fn++)
                    wmma::mma_sync(acc[fm][fn], afh[fm], bfh[fn], acc[fm][fn]);
#pragma unroll
            for (int fm = 0; fm < 2; fm++)
                wmma::load_matrix_sync(afl[fm], al_sm + (wm0 + fm * 16) * LDA + kk, LDA);
#pragma unroll
            for (int fm = 0; fm < 2; fm++)
#pragma unroll
                for (int fn = 0; fn < 4; fn++)
                    wmma::mma_sync(acc[fm][fn], afl[fm], bfh[fn], acc[fm][fn]);
#pragma unroll
            for (int fn = 0; fn < 4; fn++)
                wmma::load_matrix_sync(bfl[fn], wl_sm + (wn0 + fn * 16) * LDA + kk, LDA);
#pragma unroll
            for (int fm = 0; fm < 2; fm++)
#pragma unroll
                for (int fn = 0; fn < 4; fn++)
                    wmma::mma_sync(acc[fm][fn], afh[fm], bfl[fn], acc[fm][fn]);
        }
        __syncthreads();   // all warps done reading stage s before iter it+1 overwrites it
    }

    // ---- epilogue: frags -> smem -> (bias+gprob) -> scratch (coalesced f4) ----
    float* epi = (float*)smem;
#pragma unroll
    for (int fm = 0; fm < 2; fm++)
#pragma unroll
        for (int fn = 0; fn < 4; fn++)
            wmma::store_matrix_sync(epi + (wm0 + fm * 16) * LDE + wn0 + fn * 16,
                                    acc[fm][fn], LDE, wmma::mem_row_major);
    __syncthreads();

#pragma unroll
    for (int i = 0; i < 16; i++) {
        int idx = i * 256 + t;
        int r  = idx >> 5;
        int c4 = (idx & 31) * 4;
        float4 v = *(float4*)(epi + r * LDE + c4);
        int n = n0 + c4;
        float gp = __ldg(gprob + (size_t)(row0 + r) * 16 + (n >> 6));
        v.x = (v.x + __ldg(bias + n + 0)) * gp;
        v.y = (v.y + __ldg(bias + n + 1)) * gp;
        v.z = (v.z + __ldg(bias + n + 2)) * gp;
        v.w = (v.w + __ldg(bias + n + 3)) * gp;
        *(float4*)(g_scratch + (size_t)(row0 + r) * NCOLS + n) = v;
    }
}

// ---- scatter: 8-row tiles, 4 CTAs/SM, class-outer/row-inner gather ----
__global__ void __launch_bounds__(256, 4)
mhc_scatter(float* __restrict__ out) {
    extern __shared__ char smem[];
    float* wsm    = (float*)(smem + SC_WSM);
    int*   off_sm = (int*)(smem + SC_OFF);
    int*   src_sm = (int*)(smem + SC_SRC);
    const int t = threadIdx.x;
    const int r0 = blockIdx.x * SROWS;

    for (int i = t; i <= NCLS; i += 256) off_sm[i] = g_cls_off[i];
    for (int i = t; i < NCOLS; i += 256) src_sm[i] = g_cls_src[i];

    const float4* src = (const float4*)(g_scratch + (size_t)r0 * NCOLS);
    float4* dst4 = (float4*)wsm;
#pragma unroll
    for (int i = 0; i < SROWS * NCOLS / 4 / 256; i++)
        dst4[i * 256 + t] = src[i * 256 + t];
    __syncthreads();

    for (int c = t; c < NCLS; c += 256) {
        int s0 = off_sm[c], s1 = off_sm[c + 1];
        float* ocol = out + (size_t)r0 * NCLS + c;
        if (s1 == s0) {
#pragma unroll
            for (int r = 0; r < SROWS; r++) ocol[(size_t)r * NCLS] = 0.f;
        } else if (s1 == s0 + 1) {
            int src0 = src_sm[s0];
#pragma unroll
            for (int r = 0; r < SROWS; r++)
                ocol[(size_t)r * NCLS] = wsm[r * NCOLS + src0];
        } else {
#pragma unroll
            for (int r = 0; r < SROWS; r++) {
                float s = 0.f;
                for (int k = s0; k < s1; k++) s += wsm[r * NCOLS + src_sm[k]];
                ocol[(size_t)r * NCLS] = s;
            }
        }
    }
}

extern "C" void kernel_launch(void* const* d_in, const int* in_sizes, int n_in,
                              void* d_out, int out_size) {
    const float* features = (const float*)d_in[0];
    const float* gprob    = (const float*)d_in[1];
    const float* W        = (const float*)d_in[2];
    const float* bias     = (const float*)d_in[3];
    const int*   labels   = (const int*)d_in[4];
    float* out = (float*)d_out;

    static __nv_bfloat16 *hA, *lA, *hW, *lW;
    static bool init = false;
    if (!init) {
        cudaGetSymbolAddress((void**)&hA, g_Ahi);
        cudaGetSymbolAddress((void**)&lA, g_Alo);
        cudaGetSymbolAddress((void**)&hW, g_Whi);
        cudaGetSymbolAddress((void**)&lW, g_Wlo);
        cudaFuncSetAttribute(mhc_gemm, cudaFuncAttributeMaxDynamicSharedMemorySize, SMEM_GEMM);
        cudaFuncSetAttribute(mhc_scatter, cudaFuncAttributeMaxDynamicSharedMemorySize, SMEM_SCAT);
        init = true;
    }

    prep_kernel<<<1, 1024>>>(labels);
    prep_split<<<A_BLOCKS + (NCOLS * FDIM) / 1024, 256>>>(features, W, hA, lA, hW, lW);

    dim3 grid(NCOLS / BN, B_ROWS / BM);
    mhc_gemm<<<grid, 256, SMEM_GEMM>>>(gprob, bias);
    mhc_scatter<<<B_ROWS / SROWS, 256, SMEM_SCAT>>>(out);
}